// round 14
// baseline (speedup 1.0000x reference)
#include <cuda_runtime.h>
#include <cuda_bf16.h>
#include <cstdint>

// ============================================================================
// TNLayer, round 14: SHUFFLE-FREE h0 via N-replicated GEMM1 weights.
// B0 has 5 blocks of 8 cols; block r, col n -> b = 2r + (n&1). Thread t's
// accumulator cols {2t,2t+1} therefore hold h0[2r], h0[2r+1] for every r:
// all 10 h0 values are THREAD-LOCAL after GEMM1. The epilogue's h0-broadcast
// and o89-select shuffles (64 of 80 SHFL per 32-sample tile) disappear.
// Base: round-11 structure (M=32/warp, sequential sub-tiles, single-buffered
// per-warp cp.async, dense 224B A rows, fragment-major B1), occ 4.
//
//  h0[n,b]   = sum_i x0[n,i] t0[i,b]              (GEMM1: 5 repl. blocks, K=32)
//  h1[n,b,o] = sum_j x1[n,j] t1[j,b,o]            (GEMM2: 13 blocks, K=32)
//  c[n,o]    = sum_b h0 * h1 + bias[o]; sigmoid
//
// B1 fragment-major blocks e = 0..12:
//   e = 0..9  : b=e, o=g                (thread-local epilogue, ZERO shuffles)
//   e = 10+q  : b=4q+t, o=8+(c&1)       (local h0 select + quad bfly reduce)
// ============================================================================

#define NTHREADS 128
#define NTILES   8192             // 1048576 / 128
#define GRID_X   592              // 148 SMs * 4 persistent CTAs
#define A_STRIDE 224              // bytes per A row = 56 f32, dense
#define A_BUF    (32 * A_STRIDE)  // 7168 B single stage per warp
#define SBF_OFF  (4 * A_BUF + 16) // 28688 (16B zero guard)
#define SMEM_TOTAL (SBF_OFF + 13 * 512)   // 35344

static __device__ __forceinline__ uint32_t smem_u32(const void* p) {
    uint32_t a;
    asm("{ .reg .u64 t; cvta.to.shared.u64 t, %1; cvt.u32.u64 %0, t; }"
        : "=r"(a) : "l"(p));
    return a;
}
static __device__ __forceinline__ void cp_async16(uint32_t dst, const void* src) {
    asm volatile("cp.async.cg.shared.global [%0], [%1], 16;" :: "r"(dst), "l"(src));
}
static __device__ __forceinline__ void cp_commit() {
    asm volatile("cp.async.commit_group;" ::: "memory");
}
template <int N> static __device__ __forceinline__ void cp_wait() {
    asm volatile("cp.async.wait_group %0;" :: "n"(N) : "memory");
}
static __device__ __forceinline__ void mma_bf16(float& c0, float& c1, float& c2, float& c3,
                                                uint32_t a0, uint32_t a1, uint32_t a2, uint32_t a3,
                                                uint32_t b0, uint32_t b1) {
    asm volatile(
        "mma.sync.aligned.m16n8k16.row.col.f32.bf16.bf16.f32 "
        "{%0,%1,%2,%3}, {%4,%5,%6,%7}, {%8,%9}, {%0,%1,%2,%3};"
        : "+f"(c0), "+f"(c1), "+f"(c2), "+f"(c3)
        : "r"(a0), "r"(a1), "r"(a2), "r"(a3), "r"(b0), "r"(b1));
}
static __device__ __forceinline__ uint32_t packbf(float lo, float hi) {
    __nv_bfloat162 p = __floats2bfloat162_rn(lo, hi);
    return *reinterpret_cast<uint32_t*>(&p);
}
static __device__ __forceinline__ float sigmoidf_(float c) {
    return __fdividef(1.0f, 1.0f + __expf(-c));
}

__global__ void __launch_bounds__(NTHREADS, 4)
tn_kernel(const float* __restrict__ x,
          const float* __restrict__ t0,
          const float* __restrict__ t1,
          const float* __restrict__ bias,
          float* __restrict__ out)
{
    __shared__ __align__(16) uint8_t smem[SMEM_TOTAL];
    uint8_t* sBf = smem + SBF_OFF;

    const int tid  = threadIdx.x;
    const int lane = tid & 31;
    const int w    = tid >> 5;
    const int g    = lane >> 2;     // 0..7
    const int t    = lane & 3;      // 0..3
    const int r0   = w * 32;

    // ---------------- one-time setup ----------------
    for (int i = tid; i < SBF_OFF / 4; i += NTHREADS)
        ((uint32_t*)smem)[i] = 0u;

    // B1 fragment-major fill: word wd -> j0 = 2*tt + 8*wd
    for (int idx = tid; idx < 13 * 128; idx += NTHREADS) {
        int e = idx >> 7, ln = (idx >> 2) & 31, wd = idx & 3;
        int gg = ln >> 2, tt = ln & 3;
        int j0 = 2 * tt + 8 * wd;
        int b, o;
        if (e < 10) { b = e; o = gg; }
        else        { int q = e - 10; b = 4 * q + (gg >> 1); o = 8 + (gg & 1); }
        float f0 = 0.f, f1 = 0.f;
        if (b < 10) {
            if (j0 < 28)     f0 = t1[j0 * 100 + b * 10 + o];
            if (j0 + 1 < 28) f1 = t1[(j0 + 1) * 100 + b * 10 + o];
        }
        ((uint32_t*)sBf)[idx] = packbf(f0, f1);
    }

    // B0 N-REPLICATED fragments in registers: block r supplies col n -> b=2r+(n&1)
    // fragment of lane (g,t): n = g, k = 2t + 16kb + {0,1} / {8,9}
    auto T0 = [&](int i, int b) -> float {
        return (i < 28) ? __ldg(t0 + i * 10 + b) : 0.f;
    };
    uint32_t b0r[5][2][2];
#pragma unroll
    for (int r = 0; r < 5; r++) {
        const int bv = 2 * r + (g & 1);
#pragma unroll
        for (int kb = 0; kb < 2; kb++) {
            int k = 2 * t + 16 * kb;
            b0r[r][kb][0] = packbf(T0(k, bv),     T0(k + 1, bv));
            b0r[r][kb][1] = packbf(T0(k + 8, bv), T0(k + 9, bv));
        }
    }
    const float bs0 = __ldg(bias + 2 * t);
    const float bs1 = __ldg(bias + 2 * t + 1);
    const float bs8 = __ldg(bias + 8);
    const float bs9 = __ldg(bias + 9);
    __syncthreads();

    uint8_t* aW = smem + w * A_BUF;
    const uint32_t aWu = smem_u32(aW);

    // per-warp coalesced prefetch: 448 float4, perfectly linear
    auto prefetch = [&](int tl) {
        const float4* src = (const float4*)x + (size_t)tl * 1792 + r0 * 14;
#pragma unroll
        for (int i = 0; i < 14; i++) {
            int idx = lane + i * 32;
            cp_async16(aWu + idx * 16, src + idx);
        }
        cp_commit();
    };

    int tile = blockIdx.x;
    prefetch(tile);

    // ---------------- warp-independent tile loop ----------------
    for (; tile < NTILES; tile += GRID_X) {
        cp_wait<0>();
        __syncwarp();
        const int c0i = 2 * t;

#pragma unroll 1
        for (int s = 0; s < 2; s++) {
            const float* Ag = (const float*)(aW + (s * 16 + g) * A_STRIDE);
            const float* Ah = (const float*)(aW + (s * 16 + g + 8) * A_STRIDE);

            // ---- A fragments ----
            uint32_t ha[2][4], xa[2][4];
#pragma unroll
            for (int kb = 0; kb < 2; kb++) {
                const int k0 = c0i + 16 * kb;
                float2 v0 = *(const float2*)(Ag + k0);
                float2 v1 = *(const float2*)(Ah + k0);
                float2 v2 = *(const float2*)(Ag + k0 + 8);
                float2 v3 = *(const float2*)(Ah + k0 + 8);
                ha[kb][0] = packbf(v0.x, v0.y);
                ha[kb][1] = packbf(v1.x, v1.y);
                ha[kb][2] = packbf(v2.x, v2.y);
                ha[kb][3] = packbf(v3.x, v3.y);
                const int k1 = k0 + 28;   // overflow -> zero-B slots / guard
                float2 w0 = *(const float2*)(Ag + k1);
                float2 w1 = *(const float2*)(Ah + k1);
                float2 w2 = *(const float2*)(Ag + k1 + 8);
                float2 w3 = *(const float2*)(Ah + k1 + 8);
                xa[kb][0] = packbf(w0.x, w0.y);
                xa[kb][1] = packbf(w1.x, w1.y);
                xa[kb][2] = packbf(w2.x, w2.y);
                xa[kb][3] = packbf(w3.x, w3.y);
            }

            if (s == 1) {
                int nt = tile + GRID_X;
                if (nt < NTILES) prefetch(nt);
            }

            // ---- GEMM1: replicated blocks -> ALL h0 thread-local ----
            // h0a[r][0] = h0[2r]   (row g)    h0a[r][1] = h0[2r+1] (row g)
            // h0a[r][2] = h0[2r]   (row g+8)  h0a[r][3] = h0[2r+1] (row g+8)
            float h0a[5][4];
#pragma unroll
            for (int r = 0; r < 5; r++) {
                h0a[r][0] = 0.f; h0a[r][1] = 0.f; h0a[r][2] = 0.f; h0a[r][3] = 0.f;
#pragma unroll
                for (int kb = 0; kb < 2; kb++)
                    mma_bf16(h0a[r][0], h0a[r][1], h0a[r][2], h0a[r][3],
                             ha[kb][0], ha[kb][1], ha[kb][2], ha[kb][3],
                             b0r[r][kb][0], b0r[r][kb][1]);
            }

            // ---- GEMM2 even blocks: fully shuffle-free contraction ----
            float pA[4] = {0, 0, 0, 0};
#pragma unroll
            for (int e = 0; e < 10; e++) {
                uint4 bv = *(const uint4*)(sBf + e * 512 + lane * 16);
                float c0 = 0, c1 = 0, c2 = 0, c3 = 0;
                mma_bf16(c0, c1, c2, c3,
                         xa[0][0], xa[0][1], xa[0][2], xa[0][3], bv.x, bv.y);
                mma_bf16(c0, c1, c2, c3,
                         xa[1][0], xa[1][1], xa[1][2], xa[1][3], bv.z, bv.w);
                const float h0g_e = h0a[e >> 1][e & 1];
                const float h0h_e = h0a[e >> 1][2 + (e & 1)];
                pA[0] = fmaf(h0g_e, c0, pA[0]);
                pA[1] = fmaf(h0g_e, c1, pA[1]);
                pA[2] = fmaf(h0h_e, c2, pA[2]);
                pA[3] = fmaf(h0h_e, c3, pA[3]);
            }

            // ---- GEMM2 o89 blocks: b = 4q + t (local h0), quad bfly ----
            float p89[4] = {0, 0, 0, 0};
#pragma unroll
            for (int q = 0; q < 3; q++) {
                uint4 bv = *(const uint4*)(sBf + (10 + q) * 512 + lane * 16);
                float c0 = 0, c1 = 0, c2 = 0, c3 = 0;
                mma_bf16(c0, c1, c2, c3,
                         xa[0][0], xa[0][1], xa[0][2], xa[0][3], bv.x, bv.y);
                mma_bf16(c0, c1, c2, c3,
                         xa[1][0], xa[1][1], xa[1][2], xa[1][3], bv.z, bv.w);
                // h0[4q+t]: r = 2q + (t>>1), parity = t&1 (runtime select, no SHFL)
                const int rr = 2 * q + (t >> 1);
                const float vg = (t & 1) ? h0a[rr][1] : h0a[rr][0];
                const float vh = (t & 1) ? h0a[rr][3] : h0a[rr][2];
                p89[0] = fmaf(vg, c0, p89[0]);
                p89[1] = fmaf(vg, c1, p89[1]);
                p89[2] = fmaf(vh, c2, p89[2]);
                p89[3] = fmaf(vh, c3, p89[3]);
            }
#pragma unroll
            for (int u = 0; u < 4; u++) {
                p89[u] += __shfl_xor_sync(0xffffffffu, p89[u], 1);
                p89[u] += __shfl_xor_sync(0xffffffffu, p89[u], 2);
            }

            // ---- sigmoid + store ----
            float* og = out + ((size_t)tile * 128 + r0 + s * 16 + g) * 10;
            *(float2*)(og + 2 * t) =
                make_float2(sigmoidf_(pA[0] + bs0), sigmoidf_(pA[1] + bs1));
            *(float2*)(og + 80 + 2 * t) =
                make_float2(sigmoidf_(pA[2] + bs0), sigmoidf_(pA[3] + bs1));
            if (t == 0) {
                *(float2*)(og + 8)  =
                    make_float2(sigmoidf_(p89[0] + bs8), sigmoidf_(p89[1] + bs9));
                *(float2*)(og + 88) =
                    make_float2(sigmoidf_(p89[2] + bs8), sigmoidf_(p89[3] + bs9));
            }
        }
    }
}

extern "C" void kernel_launch(void* const* d_in, const int* in_sizes, int n_in,
                              void* d_out, int out_size) {
    const float* x    = (const float*)d_in[0];
    const float* t0   = (const float*)d_in[1];
    const float* t1   = (const float*)d_in[2];
    const float* bias = (const float*)d_in[3];
    float* out = (float*)d_out;
    tn_kernel<<<GRID_X, NTHREADS>>>(x, t0, t1, bias, out);
}

// round 15
// speedup vs baseline: 1.3337x; 1.3337x over previous
#include <cuda_runtime.h>
#include <cuda_bf16.h>
#include <cstdint>

// ============================================================================
// TNLayer, round 15: R12 (best device-side: 48.7us ncu) deepened to a 3-stage
// cp.async pipeline at occ 4. M=16/warp, dense 224B f32 A rows, LDS.64 frags,
// register-resident B0, fragment-major B1 (LDS.128). Exactly 3 commit-groups
// always in flight (empty commits at the tail) -> branch-free wait_group<2>,
// ~2.5 tiles of DRAM latency cover per warp.
//
//  h0[n,b]   = sum_i x0[n,i] t0[i,b]              (GEMM1: N=16, K=32)
//  h1[n,b,o] = sum_j x1[n,j] t1[j,b,o]            (GEMM2: N=104, K=32)
//  c[n,o]    = sum_b h0 * h1 + bias[o]; sigmoid
//
// B1 fragment-major blocks e = 0..12:
//   e = 0..9  : b=e, o=g                (thread-local epilogue)
//   e = 10+q  : b=4q+(g>>1), o=8+(g&1)  (quad bfly reduce)
// fragment word wd of lane (g,t): j pair (2t+8wd, 2t+8wd+1), zero for j>=28.
// A overflow reads (k>=56) spill into the next dense row / stage / 16B guard
// (always finite) and multiply zero B slots -> contribute exactly 0.
// ============================================================================

#define NTHREADS 128
#define NTILES   16384            // 1048576 / 64 (64 samples per CTA tile)
#define GRID_X   592              // 148 SMs * 4 persistent CTAs
#define A_STRIDE 224              // bytes per A row = 56 f32, dense
#define A_BUF    (16 * A_STRIDE)  // 3584 B per stage (16 rows)
#define NSTAGE   3
#define SBF_OFF  (4 * NSTAGE * A_BUF + 16)    // 43024 (16B zero guard)
#define SMEM_TOTAL (SBF_OFF + 13 * 512)       // 49680

static __device__ __forceinline__ uint32_t smem_u32(const void* p) {
    uint32_t a;
    asm("{ .reg .u64 t; cvta.to.shared.u64 t, %1; cvt.u32.u64 %0, t; }"
        : "=r"(a) : "l"(p));
    return a;
}
static __device__ __forceinline__ void cp_async16(uint32_t dst, const void* src) {
    asm volatile("cp.async.cg.shared.global [%0], [%1], 16;" :: "r"(dst), "l"(src));
}
static __device__ __forceinline__ void cp_commit() {
    asm volatile("cp.async.commit_group;" ::: "memory");
}
template <int N> static __device__ __forceinline__ void cp_wait() {
    asm volatile("cp.async.wait_group %0;" :: "n"(N) : "memory");
}
static __device__ __forceinline__ void mma_bf16(float& c0, float& c1, float& c2, float& c3,
                                                uint32_t a0, uint32_t a1, uint32_t a2, uint32_t a3,
                                                uint32_t b0, uint32_t b1) {
    asm volatile(
        "mma.sync.aligned.m16n8k16.row.col.f32.bf16.bf16.f32 "
        "{%0,%1,%2,%3}, {%4,%5,%6,%7}, {%8,%9}, {%0,%1,%2,%3};"
        : "+f"(c0), "+f"(c1), "+f"(c2), "+f"(c3)
        : "r"(a0), "r"(a1), "r"(a2), "r"(a3), "r"(b0), "r"(b1));
}
static __device__ __forceinline__ uint32_t packbf(float lo, float hi) {
    __nv_bfloat162 p = __floats2bfloat162_rn(lo, hi);
    return *reinterpret_cast<uint32_t*>(&p);
}
static __device__ __forceinline__ float sigmoidf_(float c) {
    return __fdividef(1.0f, 1.0f + __expf(-c));
}

__global__ void __launch_bounds__(NTHREADS, 4)
tn_kernel(const float* __restrict__ x,
          const float* __restrict__ t0,
          const float* __restrict__ t1,
          const float* __restrict__ bias,
          float* __restrict__ out)
{
    __shared__ __align__(16) uint8_t smem[SMEM_TOTAL];
    uint8_t* sBf = smem + SBF_OFF;

    const int tid  = threadIdx.x;
    const int lane = tid & 31;
    const int w    = tid >> 5;
    const int g    = lane >> 2;     // 0..7
    const int t    = lane & 3;      // 0..3
    const int r0   = w * 16;        // this warp's 16-sample base row in the tile

    // ---------------- one-time setup ----------------
    for (int i = tid; i < SBF_OFF / 4; i += NTHREADS)
        ((uint32_t*)smem)[i] = 0u;

    // B1 fragment-major fill: word wd -> j0 = 2*tt + 8*wd
    for (int idx = tid; idx < 13 * 128; idx += NTHREADS) {
        int e = idx >> 7, ln = (idx >> 2) & 31, wd = idx & 3;
        int gg = ln >> 2, tt = ln & 3;
        int j0 = 2 * tt + 8 * wd;
        int b, o;
        if (e < 10) { b = e; o = gg; }
        else        { int q = e - 10; b = 4 * q + (gg >> 1); o = 8 + (gg & 1); }
        float f0 = 0.f, f1 = 0.f;
        if (b < 10) {
            if (j0 < 28)     f0 = t1[j0 * 100 + b * 10 + o];
            if (j0 + 1 < 28) f1 = t1[(j0 + 1) * 100 + b * 10 + o];
        }
        ((uint32_t*)sBf)[idx] = packbf(f0, f1);
    }

    // B0 fragments in registers (k = 2t + 16kb + {0,1,8,9})
    auto T0 = [&](int i, int b) -> float {
        return (i < 28 && b < 10) ? __ldg(t0 + i * 10 + b) : 0.f;
    };
    uint32_t gb[2][2], fb[2][2];
#pragma unroll
    for (int kb = 0; kb < 2; kb++) {
        int k = 2 * t + 16 * kb;
        gb[kb][0] = packbf(T0(k, g),     T0(k + 1, g));
        gb[kb][1] = packbf(T0(k + 8, g), T0(k + 9, g));
        fb[kb][0] = packbf(T0(k, 8 + g),     T0(k + 1, 8 + g));
        fb[kb][1] = packbf(T0(k + 8, 8 + g), T0(k + 9, 8 + g));
    }
    const float bs0 = __ldg(bias + 2 * t);
    const float bs1 = __ldg(bias + 2 * t + 1);
    const float bs8 = __ldg(bias + 8);
    const float bs9 = __ldg(bias + 9);
    __syncthreads();

    uint8_t* aW = smem + w * (NSTAGE * A_BUF);
    const uint32_t aBase = smem_u32(aW);

    // per-warp coalesced prefetch (ALWAYS commits a group, even if empty,
    // so exactly NSTAGE groups are in flight and wait_group<2> is exact)
    auto prefetch = [&](int tl, uint32_t dstu) {
        if (tl < NTILES) {
            const float4* src = (const float4*)x + (size_t)tl * 896 + r0 * 14;
#pragma unroll
            for (int i = 0; i < 7; i++) {
                int idx = lane + i * 32;
                cp_async16(dstu + idx * 16, src + idx);
            }
        }
        cp_commit();
    };

    int tile = blockIdx.x;
    uint32_t u0 = aBase, u1 = aBase + A_BUF, u2 = aBase + 2 * A_BUF;
    prefetch(tile,              u0);
    prefetch(tile + GRID_X,     u1);
    prefetch(tile + 2 * GRID_X, u2);

    // ---------------- warp-independent, 3-deep pipelined tile loop ----------
    for (; tile < NTILES; tile += GRID_X) {
        cp_wait<2>();            // completes exactly the current tile's group
        __syncwarp();

        const float* Ag = (const float*)((uint8_t*)0 + u0 - u0) /*dummy*/;
        (void)Ag;
        const uint8_t* ab = (const uint8_t*)smem + (u0 - smem_u32(smem));
        const float* Agr = (const float*)(ab + g * A_STRIDE);
        const float* Ahr = (const float*)(ab + (g + 8) * A_STRIDE);
        const int c0i = 2 * t;

        // ---- A fragments + GEMM1 (B in registers) ----
        float eA[4] = {0, 0, 0, 0};   // h0 cols 0..7  (b = 2t,2t+1)
        float fA[4] = {0, 0, 0, 0};   // h0 cols 8..15 (b = 8+2t)
        uint32_t xa[2][4];            // h1 A frags [kb][slot]
#pragma unroll
        for (int kb = 0; kb < 2; kb++) {
            const int k0 = c0i + 16 * kb;
            float2 v0 = *(const float2*)(Agr + k0);
            float2 v1 = *(const float2*)(Ahr + k0);
            float2 v2 = *(const float2*)(Agr + k0 + 8);
            float2 v3 = *(const float2*)(Ahr + k0 + 8);
            uint32_t a0 = packbf(v0.x, v0.y);
            uint32_t a1 = packbf(v1.x, v1.y);
            uint32_t a2 = packbf(v2.x, v2.y);
            uint32_t a3 = packbf(v3.x, v3.y);
            mma_bf16(eA[0], eA[1], eA[2], eA[3],
                     a0, a1, a2, a3, gb[kb][0], gb[kb][1]);
            mma_bf16(fA[0], fA[1], fA[2], fA[3],
                     a0, a1, a2, a3, fb[kb][0], fb[kb][1]);
            const int k1 = k0 + 28;   // overflow -> zero-B slots / guard
            float2 w0 = *(const float2*)(Agr + k1);
            float2 w1 = *(const float2*)(Ahr + k1);
            float2 w2 = *(const float2*)(Agr + k1 + 8);
            float2 w3 = *(const float2*)(Ahr + k1 + 8);
            xa[kb][0] = packbf(w0.x, w0.y);
            xa[kb][1] = packbf(w1.x, w1.y);
            xa[kb][2] = packbf(w2.x, w2.y);
            xa[kb][3] = packbf(w3.x, w3.y);
        }

        // ---- this stage's reads done: refill it for tile+3G, rotate ----
        prefetch(tile + NSTAGE * GRID_X, u0);
        { uint32_t tmp = u0; u0 = u1; u1 = u2; u2 = tmp; }

        // ---- GEMM2 even blocks (B1 LDS.128), thread-local contraction ----
        float pA[4] = {0, 0, 0, 0};
#pragma unroll
        for (int e = 0; e < 10; e++) {
            uint4 bv = *(const uint4*)(sBf + e * 512 + lane * 16);
            float c0 = 0, c1 = 0, c2 = 0, c3 = 0;
            mma_bf16(c0, c1, c2, c3,
                     xa[0][0], xa[0][1], xa[0][2], xa[0][3], bv.x, bv.y);
            mma_bf16(c0, c1, c2, c3,
                     xa[1][0], xa[1][1], xa[1][2], xa[1][3], bv.z, bv.w);
            float h0g_e, h0h_e;
            if (e < 8) {
                h0g_e = __shfl_sync(0xffffffffu, (e & 1) ? eA[1] : eA[0], e >> 1, 4);
                h0h_e = __shfl_sync(0xffffffffu, (e & 1) ? eA[3] : eA[2], e >> 1, 4);
            } else {
                h0g_e = __shfl_sync(0xffffffffu, (e & 1) ? fA[1] : fA[0], 0, 4);
                h0h_e = __shfl_sync(0xffffffffu, (e & 1) ? fA[3] : fA[2], 0, 4);
            }
            pA[0] = fmaf(h0g_e, c0, pA[0]);
            pA[1] = fmaf(h0g_e, c1, pA[1]);
            pA[2] = fmaf(h0h_e, c2, pA[2]);
            pA[3] = fmaf(h0h_e, c3, pA[3]);
        }

        // ---- GEMM2 o89 blocks: b = 4q + t, quad bfly reduce ----
        float p89[4] = {0, 0, 0, 0};
#pragma unroll
        for (int q = 0; q < 3; q++) {
            uint4 bv = *(const uint4*)(sBf + (10 + q) * 512 + lane * 16);
            float c0 = 0, c1 = 0, c2 = 0, c3 = 0;
            mma_bf16(c0, c1, c2, c3,
                     xa[0][0], xa[0][1], xa[0][2], xa[0][3], bv.x, bv.y);
            mma_bf16(c0, c1, c2, c3,
                     xa[1][0], xa[1][1], xa[1][2], xa[1][3], bv.z, bv.w);
            const int srcl = 2 * q + (t >> 1);
            float v0 = __shfl_sync(0xffffffffu, eA[0], srcl, 4);
            float v1 = __shfl_sync(0xffffffffu, eA[1], srcl, 4);
            float v2 = __shfl_sync(0xffffffffu, eA[2], srcl, 4);
            float v3 = __shfl_sync(0xffffffffu, eA[3], srcl, 4);
            float vg = (t & 1) ? v1 : v0;
            float vh = (t & 1) ? v3 : v2;
            p89[0] = fmaf(vg, c0, p89[0]);
            p89[1] = fmaf(vg, c1, p89[1]);
            p89[2] = fmaf(vh, c2, p89[2]);
            p89[3] = fmaf(vh, c3, p89[3]);
        }
#pragma unroll
        for (int u = 0; u < 4; u++) {
            p89[u] += __shfl_xor_sync(0xffffffffu, p89[u], 1);
            p89[u] += __shfl_xor_sync(0xffffffffu, p89[u], 2);
        }

        // ---- sigmoid + store ----
        float* og = out + ((size_t)tile * 64 + r0 + g) * 10;
        *(float2*)(og + 2 * t) =
            make_float2(sigmoidf_(pA[0] + bs0), sigmoidf_(pA[1] + bs1));
        *(float2*)(og + 80 + 2 * t) =
            make_float2(sigmoidf_(pA[2] + bs0), sigmoidf_(pA[3] + bs1));
        if (t == 0) {
            *(float2*)(og + 8)  =
                make_float2(sigmoidf_(p89[0] + bs8), sigmoidf_(p89[1] + bs9));
            *(float2*)(og + 88) =
                make_float2(sigmoidf_(p89[2] + bs8), sigmoidf_(p89[3] + bs9));
        }
    }
}

extern "C" void kernel_launch(void* const* d_in, const int* in_sizes, int n_in,
                              void* d_out, int out_size) {
    const float* x    = (const float*)d_in[0];
    const float* t0   = (const float*)d_in[1];
    const float* t1   = (const float*)d_in[2];
    const float* bias = (const float*)d_in[3];
    float* out = (float*)d_out;
    tn_kernel<<<GRID_X, NTHREADS>>>(x, t0, t1, bias, out);
}

// round 16
// speedup vs baseline: 1.4252x; 1.0686x over previous
#include <cuda_runtime.h>
#include <cuda_bf16.h>
#include <cstdint>

// ============================================================================
// TNLayer, round 16: the proven-optimal round-8 configuration, resubmitted.
// Single-buffered per-warp cp.async A stage (cp.async smem writes land at
// data-return, so refilling the same buffer after the fragment LDS is safe),
// M=32 samples/warp (B1 amortized over both sub-tiles), register-resident B0,
// fragment-major B1 (one LDS.128 per block), 4 CTAs/SM, zero CTA barriers in
// the tile loop. Best measured: 53.0 us bench / 48.5 us ncu.
//
//  h0[n,b]   = sum_i x0[n,i] t0[i,b]              (GEMM1: N=16, K=32)
//  h1[n,b,o] = sum_j x1[n,j] t1[j,b,o]            (GEMM2: N=104, K=32)
//  c[n,o]    = sum_b h0 * h1 + bias[o]; sigmoid
//
// B1 fragment-major blocks e = 0..12:
//   e = 0..9  : b=e, o=g                (thread-local epilogue)
//   e = 10+q  : b=4q+(g>>1), o=8+(g&1)  (quad bfly reduce)
// fragment word wd of lane (g,t): j pair (2t+8wd, 2t+8wd+1), zero for j>=28.
// A overflow reads (k>=56) land in the next dense row (or the zeroed 16B
// guard) and multiply zero B slots -> contribute exactly 0.
// ============================================================================

#define NTHREADS 128
#define NTILES   8192             // 1048576 / 128
#define GRID_X   592              // 148 SMs * 4 persistent CTAs
#define A_STRIDE 224              // bytes per A row = 56 f32, dense
#define A_BUF    (32 * A_STRIDE)  // 7168 B single stage per warp
#define SBF_OFF  (4 * A_BUF + 16) // 16B zero guard after A region
#define SMEM_TOTAL (SBF_OFF + 13 * 512)   // 35344

static __device__ __forceinline__ uint32_t smem_u32(const void* p) {
    uint32_t a;
    asm("{ .reg .u64 t; cvta.to.shared.u64 t, %1; cvt.u32.u64 %0, t; }"
        : "=r"(a) : "l"(p));
    return a;
}
static __device__ __forceinline__ void cp_async16(uint32_t dst, const void* src) {
    asm volatile("cp.async.cg.shared.global [%0], [%1], 16;" :: "r"(dst), "l"(src));
}
static __device__ __forceinline__ void cp_commit() {
    asm volatile("cp.async.commit_group;" ::: "memory");
}
template <int N> static __device__ __forceinline__ void cp_wait() {
    asm volatile("cp.async.wait_group %0;" :: "n"(N) : "memory");
}
static __device__ __forceinline__ void mma_bf16(float& c0, float& c1, float& c2, float& c3,
                                                uint32_t a0, uint32_t a1, uint32_t a2, uint32_t a3,
                                                uint32_t b0, uint32_t b1) {
    asm volatile(
        "mma.sync.aligned.m16n8k16.row.col.f32.bf16.bf16.f32 "
        "{%0,%1,%2,%3}, {%4,%5,%6,%7}, {%8,%9}, {%0,%1,%2,%3};"
        : "+f"(c0), "+f"(c1), "+f"(c2), "+f"(c3)
        : "r"(a0), "r"(a1), "r"(a2), "r"(a3), "r"(b0), "r"(b1));
}
static __device__ __forceinline__ uint32_t packbf(float lo, float hi) {
    __nv_bfloat162 p = __floats2bfloat162_rn(lo, hi);
    return *reinterpret_cast<uint32_t*>(&p);
}
static __device__ __forceinline__ float sigmoidf_(float c) {
    return __fdividef(1.0f, 1.0f + __expf(-c));
}

__global__ void __launch_bounds__(NTHREADS, 4)
tn_kernel(const float* __restrict__ x,
          const float* __restrict__ t0,
          const float* __restrict__ t1,
          const float* __restrict__ bias,
          float* __restrict__ out)
{
    __shared__ __align__(16) uint8_t smem[SMEM_TOTAL];
    uint8_t* sBf = smem + SBF_OFF;

    const int tid  = threadIdx.x;
    const int lane = tid & 31;
    const int w    = tid >> 5;
    const int g    = lane >> 2;     // 0..7
    const int t    = lane & 3;      // 0..3
    const int r0   = w * 32;

    // ---------------- one-time setup ----------------
    // zero A region + guard (makes any overflow/tail read finite)
    for (int i = tid; i < SBF_OFF / 4; i += NTHREADS)
        ((uint32_t*)smem)[i] = 0u;

    // B1 fragment-major fill: idx = e*128 + lane*4 + word
    for (int idx = tid; idx < 13 * 128; idx += NTHREADS) {
        int e = idx >> 7, ln = (idx >> 2) & 31, wd = idx & 3;
        int gg = ln >> 2, tt = ln & 3;
        int j0 = 2 * tt + 8 * wd;
        int b, o;
        if (e < 10) { b = e; o = gg; }
        else        { int q = e - 10; b = 4 * q + (gg >> 1); o = 8 + (gg & 1); }
        float f0 = 0.f, f1 = 0.f;
        if (b < 10) {
            if (j0 < 28)     f0 = t1[j0 * 100 + b * 10 + o];
            if (j0 + 1 < 28) f1 = t1[(j0 + 1) * 100 + b * 10 + o];
        }
        ((uint32_t*)sBf)[idx] = packbf(f0, f1);
    }

    // B0 (GEMM1) fragments into registers
    auto T0 = [&](int i, int b) -> float {
        return (i < 28 && b < 10) ? __ldg(t0 + i * 10 + b) : 0.f;
    };
    uint32_t gb[2][2], fb[2][2];
#pragma unroll
    for (int kb = 0; kb < 2; kb++) {
        int k = 2 * t + 16 * kb;
        gb[kb][0] = packbf(T0(k, g),     T0(k + 1, g));
        gb[kb][1] = packbf(T0(k + 8, g), T0(k + 9, g));
        fb[kb][0] = packbf(T0(k, 8 + g),     T0(k + 1, 8 + g));
        fb[kb][1] = packbf(T0(k + 8, 8 + g), T0(k + 9, 8 + g));
    }
    const float bs0 = __ldg(bias + 2 * t);
    const float bs1 = __ldg(bias + 2 * t + 1);
    const float bs8 = __ldg(bias + 8);
    const float bs9 = __ldg(bias + 9);
    __syncthreads();

    uint8_t* aW = smem + w * A_BUF;
    const uint32_t aWu = smem_u32(aW);

    // per-warp coalesced prefetch into the single stage (448 linear float4)
    auto prefetch = [&](int tl) {
        const float4* src = (const float4*)x + (size_t)tl * 1792 + r0 * 14;
#pragma unroll
        for (int i = 0; i < 14; i++) {
            int idx = lane + i * 32;
            cp_async16(aWu + idx * 16, src + idx);
        }
        cp_commit();
    };

    int tile = blockIdx.x;
    prefetch(tile);

    // ---------------- warp-independent tile loop ----------------
    for (; tile < NTILES; tile += GRID_X) {
        cp_wait<0>();
        __syncwarp();

        const int c0i = 2 * t;

        // ---- h0-part fragment loads + GEMM1 (B in registers) ----
        float eA[2][4] = {{0,0,0,0},{0,0,0,0}};   // h0 cols 0..7  (b = 2t,2t+1)
        float fA[2][4] = {{0,0,0,0},{0,0,0,0}};   // h0 cols 8..15 (b = 8+2t)
        uint32_t xa[2][2][4];                      // h1 A frags   [sub][kb][slot]
#pragma unroll
        for (int s = 0; s < 2; s++) {
            const float* Ag = (const float*)(aW + (s * 16 + g) * A_STRIDE);
            const float* Ah = (const float*)(aW + (s * 16 + g + 8) * A_STRIDE);
#pragma unroll
            for (int kb = 0; kb < 2; kb++) {
                const int k0 = c0i + 16 * kb;
                float2 v0 = *(const float2*)(Ag + k0);
                float2 v1 = *(const float2*)(Ah + k0);
                float2 v2 = *(const float2*)(Ag + k0 + 8);
                float2 v3 = *(const float2*)(Ah + k0 + 8);
                uint32_t a0 = packbf(v0.x, v0.y);
                uint32_t a1 = packbf(v1.x, v1.y);
                uint32_t a2 = packbf(v2.x, v2.y);
                uint32_t a3 = packbf(v3.x, v3.y);
                mma_bf16(eA[s][0], eA[s][1], eA[s][2], eA[s][3],
                         a0, a1, a2, a3, gb[kb][0], gb[kb][1]);
                mma_bf16(fA[s][0], fA[s][1], fA[s][2], fA[s][3],
                         a0, a1, a2, a3, fb[kb][0], fb[kb][1]);
                // h1 A frags (cols 28..; overflow cols hit zero-B lanes / guard)
                const int k1 = k0 + 28;
                float2 w0 = *(const float2*)(Ag + k1);
                float2 w1 = *(const float2*)(Ah + k1);
                float2 w2 = *(const float2*)(Ag + k1 + 8);
                float2 w3 = *(const float2*)(Ah + k1 + 8);
                xa[s][kb][0] = packbf(w0.x, w0.y);
                xa[s][kb][1] = packbf(w1.x, w1.y);
                xa[s][kb][2] = packbf(w2.x, w2.y);
                xa[s][kb][3] = packbf(w3.x, w3.y);
            }
        }

        // ---- all smem A reads done: refill the SAME buffer for next tile ----
        // (cp.async smem writes land at global-data return, far after these LDS)
        int nt = tile + GRID_X;
        if (nt < NTILES) prefetch(nt);

        // ---- GEMM2 even blocks (B1 via LDS.128), thread-local contraction ----
        float pA[2][4] = {{0,0,0,0},{0,0,0,0}};
#pragma unroll
        for (int e = 0; e < 10; e++) {
            uint4 bv = *(const uint4*)(sBf + e * 512 + lane * 16);
#pragma unroll
            for (int s = 0; s < 2; s++) {
                float c0 = 0, c1 = 0, c2 = 0, c3 = 0;
                mma_bf16(c0, c1, c2, c3,
                         xa[s][0][0], xa[s][0][1], xa[s][0][2], xa[s][0][3],
                         bv.x, bv.y);
                mma_bf16(c0, c1, c2, c3,
                         xa[s][1][0], xa[s][1][1], xa[s][1][2], xa[s][1][3],
                         bv.z, bv.w);
                float h0g_e, h0h_e;
                if (e < 8) {
                    h0g_e = __shfl_sync(0xffffffffu, (e & 1) ? eA[s][1] : eA[s][0], e >> 1, 4);
                    h0h_e = __shfl_sync(0xffffffffu, (e & 1) ? eA[s][3] : eA[s][2], e >> 1, 4);
                } else {
                    h0g_e = __shfl_sync(0xffffffffu, (e & 1) ? fA[s][1] : fA[s][0], 0, 4);
                    h0h_e = __shfl_sync(0xffffffffu, (e & 1) ? fA[s][3] : fA[s][2], 0, 4);
                }
                pA[s][0] = fmaf(h0g_e, c0, pA[s][0]);
                pA[s][1] = fmaf(h0g_e, c1, pA[s][1]);
                pA[s][2] = fmaf(h0h_e, c2, pA[s][2]);
                pA[s][3] = fmaf(h0h_e, c3, pA[s][3]);
            }
        }

        // ---- GEMM2 o89 blocks: b = 4q + t, quad bfly reduce ----
        float p89[2][4] = {{0,0,0,0},{0,0,0,0}};
#pragma unroll
        for (int q = 0; q < 3; q++) {
            uint4 bv = *(const uint4*)(sBf + (10 + q) * 512 + lane * 16);
            const int srcl = 2 * q + (t >> 1);
#pragma unroll
            for (int s = 0; s < 2; s++) {
                float c0 = 0, c1 = 0, c2 = 0, c3 = 0;
                mma_bf16(c0, c1, c2, c3,
                         xa[s][0][0], xa[s][0][1], xa[s][0][2], xa[s][0][3],
                         bv.x, bv.y);
                mma_bf16(c0, c1, c2, c3,
                         xa[s][1][0], xa[s][1][1], xa[s][1][2], xa[s][1][3],
                         bv.z, bv.w);
                float v0 = __shfl_sync(0xffffffffu, eA[s][0], srcl, 4);
                float v1 = __shfl_sync(0xffffffffu, eA[s][1], srcl, 4);
                float v2 = __shfl_sync(0xffffffffu, eA[s][2], srcl, 4);
                float v3 = __shfl_sync(0xffffffffu, eA[s][3], srcl, 4);
                float vg = (t & 1) ? v1 : v0;
                float vh = (t & 1) ? v3 : v2;
                p89[s][0] = fmaf(vg, c0, p89[s][0]);
                p89[s][1] = fmaf(vg, c1, p89[s][1]);
                p89[s][2] = fmaf(vh, c2, p89[s][2]);
                p89[s][3] = fmaf(vh, c3, p89[s][3]);
            }
        }
#pragma unroll
        for (int s = 0; s < 2; s++)
#pragma unroll
            for (int u = 0; u < 4; u++) {
                p89[s][u] += __shfl_xor_sync(0xffffffffu, p89[s][u], 1);
                p89[s][u] += __shfl_xor_sync(0xffffffffu, p89[s][u], 2);
            }

        // ---- sigmoid + store ----
#pragma unroll
        for (int s = 0; s < 2; s++) {
            float* og = out + ((size_t)tile * 128 + r0 + s * 16 + g) * 10;
            *(float2*)(og + 2 * t) =
                make_float2(sigmoidf_(pA[s][0] + bs0), sigmoidf_(pA[s][1] + bs1));
            *(float2*)(og + 80 + 2 * t) =
                make_float2(sigmoidf_(pA[s][2] + bs0), sigmoidf_(pA[s][3] + bs1));
            if (t == 0) {
                *(float2*)(og + 8)  =
                    make_float2(sigmoidf_(p89[s][0] + bs8), sigmoidf_(p89[s][1] + bs9));
                *(float2*)(og + 88) =
                    make_float2(sigmoidf_(p89[s][2] + bs8), sigmoidf_(p89[s][3] + bs9));
            }
        }
    }
}

extern "C" void kernel_launch(void* const* d_in, const int* in_sizes, int n_in,
                              void* d_out, int out_size) {
    const float* x    = (const float*)d_in[0];
    const float* t0   = (const float*)d_in[1];
    const float* t1   = (const float*)d_in[2];
    const float* bias = (const float*)d_in[3];
    float* out = (float*)d_out;
    tn_kernel<<<GRID_X, NTHREADS>>>(x, t0, t1, bias, out);
}